// round 13
// baseline (speedup 1.0000x reference)
#include <cuda_runtime.h>
#include <math.h>

// ---------------- constants ----------------
#define EPSL      1e-7f
#define POS_THRF  0.5f
#define NEG_THRF  0.4f
#define ALPHA_F   0.25f
#define K4PI2     0.40528473456935109f   // 4 / pi^2

#define MAX_NA  806400    // N*A = 32*25200
#define MAX_NP  8192      // N*P
#define MAX_N   64
#define PMAX    128

// ---------------- scratch (static, zero at load; every replay leaves it zeroed) ----
__device__ __align__(16) signed char g_state[MAX_NA];
__device__ int                g_tidx[MAX_NA];
__device__ int                g_poslist[MAX_NA];
__device__ unsigned long long g_gtpacked[MAX_NP];   // lowq zeroes after consuming
__device__ int                g_poscnt[MAX_N];      // finalizer zeroes
__device__ int                g_npos;               // finalizer zeroes
__device__ int                g_done;               // finalizer zeroes
__device__ double             g_sums[3];            // finalizer zeroes

// ---------------- kernel 1: max-IoU assigner (lean epilogue) ----------------
// 8 anchors per thread, 128 threads/block -> 1024 anchors per block.
#define BLK_A 128
#define KPT   8

__global__ void assign_kernel(const float* __restrict__ bbox_true,
                              const float* __restrict__ anchors,
                              int N, int A, int P) {
    __shared__ float4             gbox[PMAX];
    __shared__ float              gAe[PMAX];     // area + EPS
    __shared__ int                gvalid[PMAX];
    __shared__ short              glist[PMAX];
    __shared__ int                gcnt;
    __shared__ unsigned long long gts[PMAX];

    const int n    = blockIdx.y;
    const int tid  = threadIdx.x;
    const int lane = tid & 31;

    for (int p = tid; p < P; p += BLK_A) {
        float4 b = ((const float4*)bbox_true)[n * P + p];
        gbox[p]   = b;
        gAe[p]    = (b.z - b.x) * (b.w - b.y) + EPSL;
        gvalid[p] = (b.x > 0.f) || (b.y > 0.f) || (b.z > 0.f) || (b.w > 0.f);
        gts[p]    = 0ull;
    }
    __syncthreads();
    // order-preserving compaction (argmax ties need first-occurrence order)
    if (tid == 0) {
        int c = 0;
        for (int p = 0; p < P; p++) if (gvalid[p]) glist[c++] = (short)p;
        gcnt = c;
    }
    __syncthreads();
    const int cn = gcnt;

    const int abase = blockIdx.x * (BLK_A * KPT) + tid;

    float ax1[KPT], ay1[KPT], ax2[KPT], ay2[KPT], aA[KPT], best[KPT];
    float uy1[KPT], uy2[KPT];
    int   bestp[KPT];

#pragma unroll
    for (int k = 0; k < KPT; k++) {
        int a = abase + k * BLK_A;
        best[k]  = -1.0f;
        bestp[k] = 0;
        if (a < A) {
            float4 b = ((const float4*)anchors)[a];
            ax1[k] = b.x; ay1[k] = b.y; ax2[k] = b.z; ay2[k] = b.w;
            aA[k]  = (b.z - b.x) * (b.w - b.y);
        } else {
            // degenerate box: inter<=0 -> iou = 0, never pushed to gt side
            ax1[k] = 4.0f; ay1[k] = 4.0f; ax2[k] = 4.0f; ay2[k] = 4.0f;
            aA[k]  = 0.0f;
        }
    }

    // per-(warp,k) y-extent union: warp covers 32 consecutive anchors (one row/scale)
#pragma unroll
    for (int k = 0; k < KPT; k++) {
        float lo = ay1[k], hi = ay2[k];
#pragma unroll
        for (int off = 16; off > 0; off >>= 1) {
            lo = fminf(lo, __shfl_xor_sync(0xffffffffu, lo, off));
            hi = fmaxf(hi, __shfl_xor_sync(0xffffffffu, hi, off));
        }
        uy1[k] = lo; uy2[k] = hi;
    }

    for (int ci = 0; ci < cn; ci++) {
        const int    p  = glist[ci];
        const float4 g  = gbox[p];
        const float  gA = gAe[p];

        float    m   = 0.0f;   // only iou>0 matters for gt side
        unsigned ma  = 0u;
        bool     hit = false;
#pragma unroll
        for (int k = 0; k < KPT; k++) {
            // warp-uniform y reject: skipped pairs provably have iou == 0,
            // which can never flip a positive assignment nor win the gt-side max (>0).
            if (g.w > uy1[k] && g.y < uy2[k]) {
                float iw = fminf(ax2[k], g.z) - fmaxf(ax1[k], g.x);
                float ih = fminf(ay2[k], g.w) - fmaxf(ay1[k], g.y);
                iw = fmaxf(iw, 0.0f); ih = fmaxf(ih, 0.0f);
                float inter = iw * ih;
                float iou = __fdividef(inter, aA[k] + gA - inter);
                if (iou > best[k]) { best[k] = iou; bestp[k] = p; }              // first-occurrence argmax over p
                if (iou > m)       { m = iou; ma = (unsigned)(abase + k * BLK_A); } // smallest anchor idx on tie
                hit = true;
            }
        }

        if (__ballot_sync(0xffffffffu, hit)) {
            unsigned hi    = __float_as_uint(m);                 // m>=0: bits monotone
            unsigned maxhi = __reduce_max_sync(0xffffffffu, hi);
            if (maxhi) {
                unsigned cand = (hi == maxhi) ? ma : 0xffffffffu;
                unsigned amin = __reduce_min_sync(0xffffffffu, cand);
                if (lane == 0)
                    atomicMax(&gts[p], ((unsigned long long)maxhi << 32)
                                     | (unsigned long long)(~amin));  // ~a: bigger => smaller anchor on iou tie
            }
        }
    }
    __syncthreads();

    // lean epilogue: state byte always, tidx only for positives
#pragma unroll
    for (int k = 0; k < KPT; k++) {
        int a = abase + k * BLK_A;
        if (a < A) {
            int s = (best[k] >= POS_THRF) ? 1 : ((best[k] < NEG_THRF) ? -1 : 0);
            int idx = n * A + a;
            g_state[idx] = (signed char)s;
            if (s == 1) g_tidx[idx] = bestp[k];
        }
    }
    for (int p = tid; p < P; p += BLK_A)
        if (gts[p]) atomicMax(&g_gtpacked[n * P + p], gts[p]);
}

// ---------------- kernel 2: low-quality override (warp per image) ----------
// batched 32-wide loads; set bits applied in ascending p order (last wins)
__global__ void lowq_kernel(int N, int A, int P) {
    const int n    = blockIdx.x;
    const int lane = threadIdx.x;
    if (n >= N) return;
    for (int base = 0; base < P; base += 32) {
        int p = base + lane;
        unsigned long long v = (p < P) ? g_gtpacked[n * P + p] : 0ull;
        if (p < P && v) g_gtpacked[n * P + p] = 0ull;   // self-clean for next replay
        unsigned msk = __ballot_sync(0xffffffffu, v != 0ull);
        while (msk) {
            int b = __ffs(msk) - 1;
            msk &= msk - 1;
            unsigned long long vv = __shfl_sync(0xffffffffu, v, b);
            if (lane == 0) {
                unsigned a = ~(unsigned)(vv & 0xffffffffull);
                int idx = n * A + (int)a;
                g_state[idx] = 1;
                g_tidx[idx]  = base + b;
            }
        }
    }
}

// ---------------- kernel 3: score loss + positive compaction ---------------
// 16 anchors/thread; negatives folded into one log per 16 (log of product)
#define BLK_S 128

__global__ void score_kernel(const float* __restrict__ conf_pred,
                             int N, int A) {
    const int n    = blockIdx.y;
    const int t    = blockIdx.x * BLK_S + threadIdx.x;
    const int G    = A >> 4;             // A % 16 == 0
    const int lane = threadIdx.x & 31;
    const int base = n * A + t * 16;

    int4   sv = make_int4(0, 0, 0, 0);   // s = 0 -> no contribution
    float4 c0 = make_float4(0.5f, 0.5f, 0.5f, 0.5f), c1 = c0, c2 = c0, c3 = c0;
    if (t < G) {
        sv = *(const int4*)  (g_state    + base);
        c0 = ((const float4*)(conf_pred + base))[0];
        c1 = ((const float4*)(conf_pred + base))[1];
        c2 = ((const float4*)(conf_pred + base))[2];
        c3 = ((const float4*)(conf_pred + base))[3];
    }
    unsigned words[4] = { (unsigned)sv.x, (unsigned)sv.y, (unsigned)sv.z, (unsigned)sv.w };
    float cf[16] = { c0.x, c0.y, c0.z, c0.w, c1.x, c1.y, c1.z, c1.w,
                     c2.x, c2.y, c2.z, c2.w, c3.x, c3.y, c3.z, c3.w };

    float score = 0.0f, prod = 1.0f;
    int   pcnt  = 0;

#pragma unroll
    for (int j = 0; j < 16; j++) {
        int   s  = (int)((signed char)((words[j >> 2] >> ((j & 3) * 8)) & 0xffu));
        float cp = fminf(fmaxf(cf[j], EPSL), 1.0f - EPSL);
        if (s < 0)      prod *= (1.0f - cp);   // 16 factors >= ~0.01: no underflow
        else if (s > 0) score += -__logf(cp);
        bool ispos = (s > 0);
        unsigned msk = __ballot_sync(0xffffffffu, ispos);
        if (msk) {
            int leader = __ffs(msk) - 1;
            int lbase  = 0;
            if (lane == leader) lbase = atomicAdd(&g_npos, __popc(msk));
            lbase = __shfl_sync(0xffffffffu, lbase, leader);
            if (ispos) {
                g_poslist[lbase + __popc(msk & ((1u << lane) - 1))] = base + j;
                pcnt++;
            }
        }
    }
    score += -__logf(prod);                    // sum of -log(1-cp) over negatives

    // block reduction
    const int w = threadIdx.x >> 5;
#pragma unroll
    for (int off = 16; off > 0; off >>= 1) {
        score += __shfl_down_sync(0xffffffffu, score, off);
        pcnt  += __shfl_down_sync(0xffffffffu, pcnt,  off);
    }
    __shared__ float rs[BLK_S / 32];
    __shared__ int   rc[BLK_S / 32];
    if (lane == 0) { rs[w] = score; rc[w] = pcnt; }
    __syncthreads();
    if (threadIdx.x == 0) {
        float v0 = 0.0f; int v1 = 0;
#pragma unroll
        for (int i = 0; i < BLK_S / 32; i++) { v0 += rs[i]; v1 += rc[i]; }
        if (v0 != 0.0f) atomicAdd(&g_sums[0], (double)v0);
        if (v1)         atomicAdd(&g_poscnt[n], v1);
    }
}

// ---------------- kernel 4: per-positive cls + bbox, last block finalizes ----
// Massive grid: each warp handles ~1 positive -> single memory-latency chain.
#define POS_BLOCKS 1040
#define BLK_P      256

__global__ void loss_pos_kernel(const float* __restrict__ logit_pred,
                                const float* __restrict__ bbox_pred,
                                const float* __restrict__ bbox_true,
                                const float* __restrict__ y_true,
                                float* __restrict__ out,
                                int N, int A, int P, int C) {
    const int lane   = threadIdx.x & 31;
    const int gw     = (blockIdx.x * BLK_P + threadIdx.x) >> 5;
    const int nwarps = (gridDim.x * BLK_P) >> 5;
    const int cnt    = g_npos;

    float cls = 0.0f, bb = 0.0f;

    for (int i = gw; i < cnt; i += nwarps) {
        const int idx  = g_poslist[i];
        const int n    = idx / A;
        const int t    = g_tidx[idx];
        const int trow = n * P + t;

        // CIoU (all lanes redundantly: broadcast loads, no divergence)
        float4 bt = ((const float4*)bbox_true)[trow];
        float4 bp = ((const float4*)bbox_pred)[idx];
        float ix1 = fmaxf(bt.x, bp.x), iy1 = fmaxf(bt.y, bp.y);
        float ix2 = fminf(bt.z, bp.z), iy2 = fminf(bt.w, bp.w);
        float inter = fmaxf(ix2 - ix1, 0.0f) * fmaxf(iy2 - iy1, 0.0f);
        float wt = bt.z - bt.x, ht = bt.w - bt.y;
        float wp = bp.z - bp.x, hp = bp.w - bp.y;
        float uni = wt * ht + wp * hp - inter + EPSL;
        float iou = __fdividef(inter, uni);
        float cw = fmaxf(bt.z, bp.z) - fminf(bt.x, bp.x);
        float ch = fmaxf(bt.w, bp.w) - fminf(bt.y, bp.y);
        float c2 = cw * cw + ch * ch + EPSL;
        float dx = bt.x + bt.z - bp.x - bp.z;
        float dy = bt.y + bt.w - bp.y - bp.w;
        float rho2 = (dx * dx + dy * dy) * 0.25f;
        float da = atanf(__fdividef(wt, ht + EPSL)) - atanf(__fdividef(wp, hp + EPSL));
        float v = K4PI2 * da * da;
        float alpha = __fdividef(v, 1.0f - iou + v + EPSL);
        float ciou = 1.0f - iou + __fdividef(rho2, c2) + alpha * v;
        bb += (lane == 0) ? ciou : 0.0f;

        // focal class loss: lanes stride over C
        const float* lp = logit_pred + (long)idx * C;
        const float* yt = y_true + (long)trow * C;
        for (int c = lane; c < C; c += 32) {
            float q  = fminf(fmaxf(lp[c], EPSL), 1.0f - EPSL);
            float tl = yt[c];
            float pt = tl * q + (1.0f - tl) * (1.0f - q);
            float at = tl * ALPHA_F + (1.0f - tl) * (1.0f - ALPHA_F);
            float om = 1.0f - pt;
            cls += -at * om * om * __logf(pt);
        }
    }

#pragma unroll
    for (int off = 16; off > 0; off >>= 1)
        cls += __shfl_down_sync(0xffffffffu, cls, off);
    if (lane == 0) {
        if (cls != 0.0f) atomicAdd(&g_sums[1], (double)cls);
        if (bb  != 0.0f) atomicAdd(&g_sums[2], (double)bb);
    }

    // ---- last block finalizes + self-cleans scratch ----
    __syncthreads();
    if (threadIdx.x == 0) {
        __threadfence();
        if (atomicAdd(&g_done, 1) == gridDim.x - 1) {
            double v0 = atomicAdd(&g_sums[0], 0.0);
            double v1 = atomicAdd(&g_sums[1], 0.0);
            double v2 = atomicAdd(&g_sums[2], 0.0);
            float avg = 0.0f;
            for (int nn = 0; nn < N; nn++) {
                avg += fmaxf((float)atomicAdd(&g_poscnt[nn], 0), 1.0f);
                g_poscnt[nn] = 0;
            }
            float r0 = (float)v0 / avg;
            float r1 = (float)v1 / avg;
            float r2 = (float)v2 / avg;
            out[0] = (isnan(r0) || isinf(r0)) ? 0.0f : r0;
            out[1] = (isnan(r1) || isinf(r1)) ? 0.0f : r1;
            out[2] = (isnan(r2) || isinf(r2)) ? 0.0f : r2;
            g_sums[0] = 0.0; g_sums[1] = 0.0; g_sums[2] = 0.0;
            g_npos = 0;
            g_done = 0;
        }
    }
}

// ---------------- launch ----------------
extern "C" void kernel_launch(void* const* d_in, const int* in_sizes, int n_in,
                              void* d_out, int out_size) {
    const float* y_true     = (const float*)d_in[0];  // N,P,C
    const float* bbox_true  = (const float*)d_in[1];  // N,P,4
    const float* conf_pred  = (const float*)d_in[2];  // N,A,1
    const float* logit_pred = (const float*)d_in[3];  // N,A,C
    const float* bbox_pred  = (const float*)d_in[4];  // N,A,4
    const float* anchors    = (const float*)d_in[5];  // A,4

    const int A = in_sizes[5] / 4;
    const int N = in_sizes[2] / A;
    const int P = in_sizes[1] / (N * 4);
    const int C = in_sizes[0] / (N * P);

    dim3 gA((A + BLK_A * KPT - 1) / (BLK_A * KPT), N);
    assign_kernel<<<gA, BLK_A>>>(bbox_true, anchors, N, A, P);

    lowq_kernel<<<N, 32>>>(N, A, P);

    dim3 gS((A / 16 + BLK_S - 1) / BLK_S, N);
    score_kernel<<<gS, BLK_S>>>(conf_pred, N, A);

    loss_pos_kernel<<<POS_BLOCKS, BLK_P>>>(logit_pred, bbox_pred,
                                           bbox_true, y_true,
                                           (float*)d_out, N, A, P, C);
}

// round 17
// speedup vs baseline: 1.2610x; 1.2610x over previous
#include <cuda_runtime.h>
#include <math.h>

// ---------------- constants ----------------
#define EPSL      1e-7f
#define POS_THRF  0.5f
#define NEG_THRF  0.4f
#define ALPHA_F   0.25f
#define K4PI2     0.40528473456935109f   // 4 / pi^2

#define MAX_NA  806400    // N*A = 32*25200
#define MAX_NP  8192      // N*P
#define MAX_N   64
#define PMAX    128

// ---------------- scratch (static, zero at load; every replay leaves it zeroed) ----
__device__ __align__(16) signed char g_state[MAX_NA];
__device__ int                g_tidx[MAX_NA];
__device__ int2               g_poslist[MAX_NA];    // (idx, trow) packed by score kernel
__device__ unsigned long long g_gtpacked[MAX_NP];   // lowq zeroes after consuming
__device__ int                g_poscnt[MAX_N];      // finalizer zeroes
__device__ int                g_npos;               // finalizer zeroes
__device__ int                g_done;               // finalizer zeroes
__device__ double             g_sums[3];            // finalizer zeroes

// ---------------- kernel 1: max-IoU assigner (lean epilogue) ----------------
// 8 anchors per thread, 128 threads/block -> 1024 anchors per block.
#define BLK_A 128
#define KPT   8

__global__ void assign_kernel(const float* __restrict__ bbox_true,
                              const float* __restrict__ anchors,
                              int N, int A, int P) {
    __shared__ float4             gbox[PMAX];
    __shared__ float              gAe[PMAX];     // area + EPS
    __shared__ int                gvalid[PMAX];
    __shared__ short              glist[PMAX];
    __shared__ int                gcnt;
    __shared__ unsigned long long gts[PMAX];

    const int n    = blockIdx.y;
    const int tid  = threadIdx.x;
    const int lane = tid & 31;

    for (int p = tid; p < P; p += BLK_A) {
        float4 b = ((const float4*)bbox_true)[n * P + p];
        gbox[p]   = b;
        gAe[p]    = (b.z - b.x) * (b.w - b.y) + EPSL;
        gvalid[p] = (b.x > 0.f) || (b.y > 0.f) || (b.z > 0.f) || (b.w > 0.f);
        gts[p]    = 0ull;
    }
    __syncthreads();
    // order-preserving compaction (argmax ties need first-occurrence order)
    if (tid == 0) {
        int c = 0;
        for (int p = 0; p < P; p++) if (gvalid[p]) glist[c++] = (short)p;
        gcnt = c;
    }
    __syncthreads();
    const int cn = gcnt;

    const int abase = blockIdx.x * (BLK_A * KPT) + tid;

    float ax1[KPT], ay1[KPT], ax2[KPT], ay2[KPT], aA[KPT], best[KPT];
    float uy1[KPT], uy2[KPT];
    int   bestp[KPT];

#pragma unroll
    for (int k = 0; k < KPT; k++) {
        int a = abase + k * BLK_A;
        best[k]  = -1.0f;
        bestp[k] = 0;
        if (a < A) {
            float4 b = ((const float4*)anchors)[a];
            ax1[k] = b.x; ay1[k] = b.y; ax2[k] = b.z; ay2[k] = b.w;
            aA[k]  = (b.z - b.x) * (b.w - b.y);
        } else {
            // degenerate box: inter<=0 -> iou = 0, never pushed to gt side
            ax1[k] = 4.0f; ay1[k] = 4.0f; ax2[k] = 4.0f; ay2[k] = 4.0f;
            aA[k]  = 0.0f;
        }
    }

    // per-(warp,k) y-extent union: warp covers 32 consecutive anchors (one row/scale)
#pragma unroll
    for (int k = 0; k < KPT; k++) {
        float lo = ay1[k], hi = ay2[k];
#pragma unroll
        for (int off = 16; off > 0; off >>= 1) {
            lo = fminf(lo, __shfl_xor_sync(0xffffffffu, lo, off));
            hi = fmaxf(hi, __shfl_xor_sync(0xffffffffu, hi, off));
        }
        uy1[k] = lo; uy2[k] = hi;
    }

    for (int ci = 0; ci < cn; ci++) {
        const int    p  = glist[ci];
        const float4 g  = gbox[p];
        const float  gA = gAe[p];

        float    m   = 0.0f;   // only iou>0 matters for gt side
        unsigned ma  = 0u;
        bool     hit = false;
#pragma unroll
        for (int k = 0; k < KPT; k++) {
            // warp-uniform y reject: skipped pairs provably have iou == 0,
            // which can never flip a positive assignment nor win the gt-side max (>0).
            if (g.w > uy1[k] && g.y < uy2[k]) {
                float iw = fminf(ax2[k], g.z) - fmaxf(ax1[k], g.x);
                float ih = fminf(ay2[k], g.w) - fmaxf(ay1[k], g.y);
                iw = fmaxf(iw, 0.0f); ih = fmaxf(ih, 0.0f);
                float inter = iw * ih;
                float iou = __fdividef(inter, aA[k] + gA - inter);
                if (iou > best[k]) { best[k] = iou; bestp[k] = p; }              // first-occurrence argmax over p
                if (iou > m)       { m = iou; ma = (unsigned)(abase + k * BLK_A); } // smallest anchor idx on tie
                hit = true;
            }
        }

        if (__ballot_sync(0xffffffffu, hit)) {
            unsigned hi    = __float_as_uint(m);                 // m>=0: bits monotone
            unsigned maxhi = __reduce_max_sync(0xffffffffu, hi);
            if (maxhi) {
                unsigned cand = (hi == maxhi) ? ma : 0xffffffffu;
                unsigned amin = __reduce_min_sync(0xffffffffu, cand);
                if (lane == 0)
                    atomicMax(&gts[p], ((unsigned long long)maxhi << 32)
                                     | (unsigned long long)(~amin));  // ~a: bigger => smaller anchor on iou tie
            }
        }
    }
    __syncthreads();

    // lean epilogue: state byte always, tidx only for positives
#pragma unroll
    for (int k = 0; k < KPT; k++) {
        int a = abase + k * BLK_A;
        if (a < A) {
            int s = (best[k] >= POS_THRF) ? 1 : ((best[k] < NEG_THRF) ? -1 : 0);
            int idx = n * A + a;
            g_state[idx] = (signed char)s;
            if (s == 1) g_tidx[idx] = bestp[k];
        }
    }
    for (int p = tid; p < P; p += BLK_A)
        if (gts[p]) atomicMax(&g_gtpacked[n * P + p], gts[p]);
}

// ---------------- kernel 2: low-quality override (warp per image) ----------
// batched 32-wide loads; set bits applied in ascending p order (last wins)
__global__ void lowq_kernel(int N, int A, int P) {
    const int n    = blockIdx.x;
    const int lane = threadIdx.x;
    if (n >= N) return;
    for (int base = 0; base < P; base += 32) {
        int p = base + lane;
        unsigned long long v = (p < P) ? g_gtpacked[n * P + p] : 0ull;
        if (p < P && v) g_gtpacked[n * P + p] = 0ull;   // self-clean for next replay
        unsigned msk = __ballot_sync(0xffffffffu, v != 0ull);
        while (msk) {
            int b = __ffs(msk) - 1;
            msk &= msk - 1;
            unsigned long long vv = __shfl_sync(0xffffffffu, v, b);
            if (lane == 0) {
                unsigned a = ~(unsigned)(vv & 0xffffffffull);
                int idx = n * A + (int)a;
                g_state[idx] = 1;
                g_tidx[idx]  = base + b;
            }
        }
    }
}

// ---------------- kernel 3: score loss + positive compaction ---------------
// 16 anchors/thread; negatives folded into one log per 16 (log of product).
// Positives stored as (idx, trow) int2 so loss_pos has a 1-level load chain.
#define BLK_S 128

__global__ void score_kernel(const float* __restrict__ conf_pred,
                             int N, int A, int P) {
    const int n    = blockIdx.y;
    const int t    = blockIdx.x * BLK_S + threadIdx.x;
    const int G    = A >> 4;             // A % 16 == 0
    const int lane = threadIdx.x & 31;
    const int base = n * A + t * 16;

    int4   sv = make_int4(0, 0, 0, 0);   // s = 0 -> no contribution
    float4 c0 = make_float4(0.5f, 0.5f, 0.5f, 0.5f), c1 = c0, c2 = c0, c3 = c0;
    if (t < G) {
        sv = *(const int4*)  (g_state    + base);
        c0 = ((const float4*)(conf_pred + base))[0];
        c1 = ((const float4*)(conf_pred + base))[1];
        c2 = ((const float4*)(conf_pred + base))[2];
        c3 = ((const float4*)(conf_pred + base))[3];
    }
    unsigned words[4] = { (unsigned)sv.x, (unsigned)sv.y, (unsigned)sv.z, (unsigned)sv.w };
    float cf[16] = { c0.x, c0.y, c0.z, c0.w, c1.x, c1.y, c1.z, c1.w,
                     c2.x, c2.y, c2.z, c2.w, c3.x, c3.y, c3.z, c3.w };

    float score = 0.0f, prod = 1.0f;
    int   pcnt  = 0;

#pragma unroll
    for (int j = 0; j < 16; j++) {
        int   s  = (int)((signed char)((words[j >> 2] >> ((j & 3) * 8)) & 0xffu));
        float cp = fminf(fmaxf(cf[j], EPSL), 1.0f - EPSL);
        if (s < 0)      prod *= (1.0f - cp);   // 16 factors >= ~0.01: no underflow
        else if (s > 0) score += -__logf(cp);
        bool ispos = (s > 0);
        unsigned msk = __ballot_sync(0xffffffffu, ispos);
        if (msk) {
            int leader = __ffs(msk) - 1;
            int lbase  = 0;
            if (lane == leader) lbase = atomicAdd(&g_npos, __popc(msk));
            lbase = __shfl_sync(0xffffffffu, lbase, leader);
            if (ispos) {
                int idx = base + j;
                g_poslist[lbase + __popc(msk & ((1u << lane) - 1))] =
                    make_int2(idx, n * P + g_tidx[idx]);   // tidx final (lowq already ran)
                pcnt++;
            }
        }
    }
    score += -__logf(prod);                    // sum of -log(1-cp) over negatives

    // block reduction
    const int w = threadIdx.x >> 5;
#pragma unroll
    for (int off = 16; off > 0; off >>= 1) {
        score += __shfl_down_sync(0xffffffffu, score, off);
        pcnt  += __shfl_down_sync(0xffffffffu, pcnt,  off);
    }
    __shared__ float rs[BLK_S / 32];
    __shared__ int   rc[BLK_S / 32];
    if (lane == 0) { rs[w] = score; rc[w] = pcnt; }
    __syncthreads();
    if (threadIdx.x == 0) {
        float v0 = 0.0f; int v1 = 0;
#pragma unroll
        for (int i = 0; i < BLK_S / 32; i++) { v0 += rs[i]; v1 += rc[i]; }
        if (v0 != 0.0f) atomicAdd(&g_sums[0], (double)v0);
        if (v1)         atomicAdd(&g_poscnt[n], v1);
    }
}

// ---------------- kernel 4: per-positive cls + bbox, last block finalizes ----
// prefetched flat load chain; block-level reduce -> 2 atomics per block;
// parallel (warp-wide) finalize.
#define POS_BLOCKS 296
#define BLK_P      256

__global__ void loss_pos_kernel(const float* __restrict__ logit_pred,
                                const float* __restrict__ bbox_pred,
                                const float* __restrict__ bbox_true,
                                const float* __restrict__ y_true,
                                float* __restrict__ out,
                                int N, int A, int P, int C) {
    const int lane   = threadIdx.x & 31;
    const int gw     = (blockIdx.x * BLK_P + threadIdx.x) >> 5;
    const int nwarps = (gridDim.x * BLK_P) >> 5;
    const int cnt    = g_npos;

    float cls = 0.0f, bb = 0.0f;

    int  i   = gw;
    int2 cur = (i < cnt) ? g_poslist[i] : make_int2(0, 0);
    while (i < cnt) {
        const int inx  = i + nwarps;
        int2 nxt = (inx < cnt) ? g_poslist[inx] : make_int2(0, 0);   // prefetch

        const int idx  = cur.x;
        const int trow = cur.y;

        // CIoU (all lanes redundantly: broadcast loads, no divergence)
        float4 bt = ((const float4*)bbox_true)[trow];
        float4 bp = ((const float4*)bbox_pred)[idx];
        float ix1 = fmaxf(bt.x, bp.x), iy1 = fmaxf(bt.y, bp.y);
        float ix2 = fminf(bt.z, bp.z), iy2 = fminf(bt.w, bp.w);
        float inter = fmaxf(ix2 - ix1, 0.0f) * fmaxf(iy2 - iy1, 0.0f);
        float wt = bt.z - bt.x, ht = bt.w - bt.y;
        float wp = bp.z - bp.x, hp = bp.w - bp.y;
        float uni = wt * ht + wp * hp - inter + EPSL;
        float iou = __fdividef(inter, uni);
        float cw = fmaxf(bt.z, bp.z) - fminf(bt.x, bp.x);
        float ch = fmaxf(bt.w, bp.w) - fminf(bt.y, bp.y);
        float c2 = cw * cw + ch * ch + EPSL;
        float dx = bt.x + bt.z - bp.x - bp.z;
        float dy = bt.y + bt.w - bp.y - bp.w;
        float rho2 = (dx * dx + dy * dy) * 0.25f;
        float da = atanf(__fdividef(wt, ht + EPSL)) - atanf(__fdividef(wp, hp + EPSL));
        float v = K4PI2 * da * da;
        float alpha = __fdividef(v, 1.0f - iou + v + EPSL);
        float ciou = 1.0f - iou + __fdividef(rho2, c2) + alpha * v;
        bb += (lane == 0) ? ciou : 0.0f;

        // focal class loss: lanes stride over C
        const float* lp = logit_pred + (long)idx * C;
        const float* yt = y_true + (long)trow * C;
        for (int c = lane; c < C; c += 32) {
            float q  = fminf(fmaxf(lp[c], EPSL), 1.0f - EPSL);
            float tl = yt[c];
            float pt = tl * q + (1.0f - tl) * (1.0f - q);
            float at = tl * ALPHA_F + (1.0f - tl) * (1.0f - ALPHA_F);
            float om = 1.0f - pt;
            cls += -at * om * om * __logf(pt);
        }

        cur = nxt;
        i   = inx;
    }

    // block-level reduction -> single atomic pair per block
#pragma unroll
    for (int off = 16; off > 0; off >>= 1) {
        cls += __shfl_down_sync(0xffffffffu, cls, off);
        bb  += __shfl_down_sync(0xffffffffu, bb,  off);
    }
    __shared__ float rc[BLK_P / 32], rb[BLK_P / 32];
    const int w = threadIdx.x >> 5;
    if (lane == 0) { rc[w] = cls; rb[w] = bb; }
    __syncthreads();
    if (threadIdx.x == 0) {
        float v1 = 0.0f, v2 = 0.0f;
#pragma unroll
        for (int k = 0; k < BLK_P / 32; k++) { v1 += rc[k]; v2 += rb[k]; }
        if (v1 != 0.0f) atomicAdd(&g_sums[1], (double)v1);
        if (v2 != 0.0f) atomicAdd(&g_sums[2], (double)v2);
    }

    // ---- last block finalizes (warp-parallel) + self-cleans scratch ----
    __shared__ int islast;
    __syncthreads();
    if (threadIdx.x == 0) {
        __threadfence();
        islast = (atomicAdd(&g_done, 1) == (int)gridDim.x - 1);
    }
    __syncthreads();
    if (islast && threadIdx.x < 32) {
        __threadfence();   // acquire: make all blocks' atomics visible as plain loads
        float part = 0.0f;
        for (int nn = lane; nn < N; nn += 32) {
            part += fmaxf((float)*(volatile int*)&g_poscnt[nn], 1.0f);
            g_poscnt[nn] = 0;
        }
#pragma unroll
        for (int off = 16; off > 0; off >>= 1)
            part += __shfl_down_sync(0xffffffffu, part, off);
        float avg = __shfl_sync(0xffffffffu, part, 0);
        if (lane < 3) {
            double s = *(volatile double*)&g_sums[lane];
            float  r = (float)s / avg;
            out[lane] = (isnan(r) || isinf(r)) ? 0.0f : r;
            g_sums[lane] = 0.0;
        }
        if (lane == 0) { g_npos = 0; g_done = 0; }
    }
}

// ---------------- launch ----------------
extern "C" void kernel_launch(void* const* d_in, const int* in_sizes, int n_in,
                              void* d_out, int out_size) {
    const float* y_true     = (const float*)d_in[0];  // N,P,C
    const float* bbox_true  = (const float*)d_in[1];  // N,P,4
    const float* conf_pred  = (const float*)d_in[2];  // N,A,1
    const float* logit_pred = (const float*)d_in[3];  // N,A,C
    const float* bbox_pred  = (const float*)d_in[4];  // N,A,4
    const float* anchors    = (const float*)d_in[5];  // A,4

    const int A = in_sizes[5] / 4;
    const int N = in_sizes[2] / A;
    const int P = in_sizes[1] / (N * 4);
    const int C = in_sizes[0] / (N * P);

    dim3 gA((A + BLK_A * KPT - 1) / (BLK_A * KPT), N);
    assign_kernel<<<gA, BLK_A>>>(bbox_true, anchors, N, A, P);

    lowq_kernel<<<N, 32>>>(N, A, P);

    dim3 gS((A / 16 + BLK_S - 1) / BLK_S, N);
    score_kernel<<<gS, BLK_S>>>(conf_pred, N, A, P);

    loss_pos_kernel<<<POS_BLOCKS, BLK_P>>>(logit_pred, bbox_pred,
                                           bbox_true, y_true,
                                           (float*)d_out, N, A, P, C);
}